// round 4
// baseline (speedup 1.0000x reference)
#include <cuda_runtime.h>
#include <cstddef>
#include <cstdint>

#define BB 4
#define NN 8192
#define CC 64
#define SS 2048
#define KK 32
#define R2 0.04f

#define GROUPED_OFF (BB * SS * 3)                       /* 24576 */
#define FPS_OFF (GROUPED_OFF + BB * (CC + 3) * SS * KK) /* 24576 + 17563648 */

#define CLU 4               /* CTAs per batch (one cluster) */
#define PPC (NN / CLU)      /* 2048 points per CTA */

// scratch (static device globals: no allocation in kernel_launch)
__device__ int   g_ballidx[BB * SS * KK];    // 1 MB
__device__ float g_ft[(size_t)BB * NN * CC]; // 8 MB, features transposed to (B,N,C)

// ---------------------------------------------------------------------------
// packed f32x2 helpers (Blackwell FFMA2 path — only reachable via PTX f32x2)
// ---------------------------------------------------------------------------
typedef unsigned long long u64;

__device__ __forceinline__ u64 pk2(float lo, float hi) {
    u64 r; asm("mov.b64 %0, {%1, %2};" : "=l"(r) : "f"(lo), "f"(hi)); return r;
}
__device__ __forceinline__ void upk2(u64 v, float& lo, float& hi) {
    asm("mov.b64 {%0, %1}, %2;" : "=f"(lo), "=f"(hi) : "l"(v));
}
__device__ __forceinline__ u64 add2(u64 a, u64 b) {
    u64 r; asm("add.rn.f32x2 %0, %1, %2;" : "=l"(r) : "l"(a), "l"(b)); return r;
}
__device__ __forceinline__ u64 mul2(u64 a, u64 b) {
    u64 r; asm("mul.rn.f32x2 %0, %1, %2;" : "=l"(r) : "l"(a), "l"(b)); return r;
}
__device__ __forceinline__ u64 fma2(u64 a, u64 b, u64 c) {
    u64 r; asm("fma.rn.f32x2 %0, %1, %2, %3;" : "=l"(r) : "l"(a), "l"(b), "l"(c)); return r;
}

__device__ __forceinline__ uint32_t smem_u32(const void* p) {
    uint32_t a;
    asm("{ .reg .u64 t; cvta.to.shared.u64 t, %1; cvt.u32.u64 %0, t; }"
        : "=r"(a) : "l"(p));
    return a;
}
__device__ __forceinline__ unsigned ctarank() {
    unsigned r; asm("mov.u32 %0, %%cluster_ctarank;" : "=r"(r)); return r;
}
__device__ __forceinline__ void mbar_wait_cluster(uint32_t addr, uint32_t parity) {
    asm volatile(
        "{\n\t.reg .pred P;\n\t"
        "WL_%=:\n\t"
        "mbarrier.try_wait.parity.acquire.cluster.shared::cta.b64 P, [%0], %1, 0x989680;\n\t"
        "@P bra WD_%=;\n\t"
        "bra WL_%=;\n\t"
        "WD_%=:\n\t}"
        :: "r"(addr), "r"(parity) : "memory");
}

// ---------------------------------------------------------------------------
// features (B,C,N) -> (B,N,C)
// ---------------------------------------------------------------------------
__global__ void transpose_kernel(const float* __restrict__ f) {
    __shared__ float tile[32][33];
    const int b  = blockIdx.z;
    const int n0 = blockIdx.x * 32;
    const int c0 = blockIdx.y * 32;
    const float* fb = f + (size_t)b * CC * NN;
#pragma unroll
    for (int j = 0; j < 32; j += 8)
        tile[threadIdx.y + j][threadIdx.x] =
            fb[(size_t)(c0 + threadIdx.y + j) * NN + (n0 + threadIdx.x)];
    __syncthreads();
    float* fo = g_ft + (size_t)b * NN * CC;
#pragma unroll
    for (int j = 0; j < 32; j += 8)
        fo[(size_t)(n0 + threadIdx.y + j) * CC + (c0 + threadIdx.x)] =
            tile[threadIdx.x][threadIdx.y + j];
}

// ---------------------------------------------------------------------------
// FPS: 4-CTA cluster per batch, 256 threads/CTA, 8 points/thread (f32x2 pairs).
// Per-iteration cluster argmax via DSMEM slot writes + one mbarrier (32 arrivals,
// parity-phased), double-buffered slots. No __syncthreads in the loop.
// writes new_xyz (out[0..]) and fps_idx (out[FPS_OFF..], as float)
// ---------------------------------------------------------------------------
__global__ void __launch_bounds__(256, 1) __cluster_dims__(CLU, 1, 1)
fps_kernel(const float* __restrict__ xyz, float* __restrict__ out) {
    const unsigned rank = ctarank();
    const int b = blockIdx.x / CLU;
    const float* base = xyz + (size_t)b * NN * 3;
    float* newxyz = out + (size_t)b * SS * 3;
    float* fpsout = out + FPS_OFF + (size_t)b * SS;
    const int t = threadIdx.x;
    const int lane = t & 31;
    const int warp = t >> 5;

    __shared__ u64 s_slot[2][32];        // [buf][cta*8 + warp] packed (val<<32)|idx
    __shared__ u64 s_mbar;

    const uint32_t slot_addr = smem_u32(&s_slot[0][0]);
    const uint32_t mbar_addr = smem_u32(&s_mbar);

    if (t == 0) {
        asm volatile("mbarrier.init.shared.b64 [%0], %1;"
                     :: "r"(mbar_addr), "r"(32) : "memory");
    }
    asm volatile("barrier.cluster.arrive.aligned;" ::: "memory");
    asm volatile("barrier.cluster.wait.aligned;" ::: "memory");

    // this CTA's 2048 points; pair j = (p0, p0+256), stored NEGATED
    const int pbase = (int)rank * PPC;
    u64 npx[4], npy[4], npz[4];
    float md[8];
#pragma unroll
    for (int j = 0; j < 4; j++) {
        const int p0 = pbase + t + (2 * j) * 256;
        const int p1 = p0 + 256;
        npx[j] = pk2(-base[p0 * 3 + 0], -base[p1 * 3 + 0]);
        npy[j] = pk2(-base[p0 * 3 + 1], -base[p1 * 3 + 1]);
        npz[j] = pk2(-base[p0 * 3 + 2], -base[p1 * 3 + 2]);
        md[2 * j] = 1e10f; md[2 * j + 1] = 1e10f;
    }

    float cx = base[0], cy = base[1], cz = base[2];
    if (rank == 0 && t == 0) {
        fpsout[0] = 0.0f;
        newxyz[0] = cx; newxyz[1] = cy; newxyz[2] = cz;
    }

    for (int i = 1; i < SS; i++) {
        const int buf = i & 1;
        const unsigned parity = (unsigned)((i - 1) & 1);
        const u64 cx2 = pk2(cx, cx);
        const u64 cy2 = pk2(cy, cy);
        const u64 cz2 = pk2(cz, cz);

        float m2[4];
#pragma unroll
        for (int j = 0; j < 4; j++) {
            const u64 dx = add2(cx2, npx[j]);          // cx - px
            const u64 dy = add2(cy2, npy[j]);
            const u64 dz = add2(cz2, npz[j]);
            const u64 d  = fma2(dz, dz, fma2(dy, dy, mul2(dx, dx)));
            float dl, dh; upk2(d, dl, dh);
            md[2 * j]     = fminf(md[2 * j], dl);
            md[2 * j + 1] = fminf(md[2 * j + 1], dh);
            m2[j] = fmaxf(md[2 * j], md[2 * j + 1]);
        }
        const float bv = fmaxf(fmaxf(m2[0], m2[1]), fmaxf(m2[2], m2[3]));

        // first (lowest-k => lowest global idx) occurrence of the max
        int bi = 0;
#pragma unroll
        for (int k = 7; k >= 0; k--)
            if (md[k] == bv) bi = pbase + t + k * 256;

        // warp reduce: md >= 0 so float bits are order-isomorphic to u32
        const unsigned ubv  = __float_as_uint(bv);
        const unsigned wmax = __reduce_max_sync(0xffffffffu, ubv);
        const unsigned cand = (ubv == wmax) ? (unsigned)bi : 0xffffffffu;
        const unsigned wbi  = __reduce_min_sync(0xffffffffu, cand);

        // lanes 0..3: publish this warp's winner to CTA 'lane' of the cluster
        if (lane < CLU) {
            const u64 key = ((u64)wmax << 32) | (u64)wbi;
            const uint32_t ls = slot_addr +
                (uint32_t)(buf * 32 + (int)rank * 8 + warp) * 8u;
            asm volatile(
                "{\n\t.reg .b32 rs, rb;\n\t"
                "mapa.shared::cluster.u32 rs, %0, %2;\n\t"
                "mapa.shared::cluster.u32 rb, %1, %2;\n\t"
                "st.shared::cluster.u64 [rs], %3;\n\t"
                "mbarrier.arrive.release.cluster.shared::cluster.b64 _, [rb];\n\t"
                "}" :: "r"(ls), "r"(mbar_addr), "r"(lane), "l"(key) : "memory");
        }

        mbar_wait_cluster(mbar_addr, parity);

        // every warp redundantly reduces the 32 slots
        const u64 kk = s_slot[buf][lane];
        const unsigned v = (unsigned)(kk >> 32);
        const unsigned x = (unsigned)(kk & 0xffffffffu);
        const unsigned bmax = __reduce_max_sync(0xffffffffu, v);
        const unsigned c2   = (v == bmax) ? x : 0xffffffffu;
        const int gi = (int)__reduce_min_sync(0xffffffffu, c2);

        cx = base[(size_t)gi * 3 + 0];   // same addr per warp -> L1 broadcast
        cy = base[(size_t)gi * 3 + 1];
        cz = base[(size_t)gi * 3 + 2];
        if (rank == 0 && t == 0) {
            fpsout[i] = (float)gi;
            newxyz[(size_t)i * 3 + 0] = cx;
            newxyz[(size_t)i * 3 + 1] = cy;
            newxyz[(size_t)i * 3 + 2] = cz;
        }
    }

    asm volatile("barrier.cluster.arrive.aligned;" ::: "memory");
    asm volatile("barrier.cluster.wait.aligned;" ::: "memory");
}

// ---------------------------------------------------------------------------
// ball query: one warp per center; first K hits in index order via ballot/popc,
// pad with first hit (0 if none). Early exit when K found.
// ---------------------------------------------------------------------------
__global__ void ballquery_kernel(const float* __restrict__ xyz,
                                 const float* __restrict__ out) {
    __shared__ int sidx[8][KK];
    const int w    = threadIdx.x >> 5;
    const int lane = threadIdx.x & 31;
    const int cid  = blockIdx.x * 8 + w;
    const int b = cid / SS;
    const float* c = out + (size_t)cid * 3;      // new_xyz lives at start of out
    const float cx = c[0], cy = c[1], cz = c[2];
    const float* base = xyz + (size_t)b * NN * 3;

    sidx[w][lane] = 0;
    int cnt = 0;
    for (int p0 = 0; p0 < NN && cnt < KK; p0 += 32) {
        const int p = p0 + lane;
        const float dx = base[p * 3 + 0] - cx;
        const float dy = base[p * 3 + 1] - cy;
        const float dz = base[p * 3 + 2] - cz;
        const float d2 = __fmaf_rn(dz, dz, __fmaf_rn(dy, dy, __fmul_rn(dx, dx)));
        const bool hit = d2 < R2;
        const unsigned m = __ballot_sync(0xffffffffu, hit);
        if (m) {
            if (cnt == 0) {
                const int first = p0 + (__ffs(m) - 1);
                sidx[w][lane] = first;      // pad all K slots with first hit
            }
            __syncwarp();
            if (hit) {
                const int slot = cnt + __popc(m & ((1u << lane) - 1u));
                if (slot < KK) sidx[w][slot] = p;
            }
            cnt += __popc(m);
        }
    }
    __syncwarp();
    g_ballidx[(size_t)cid * KK + lane] = sidx[w][lane];
}

// ---------------------------------------------------------------------------
// grouping: one block per center. Coalesced 256B feature-row reads via smem,
// coalesced K-contiguous channel-major writes.
// out grouped layout: (B, 3+C, S, K), channels 0..2 = recentered xyz
// ---------------------------------------------------------------------------
__global__ void group_kernel(const float* __restrict__ xyz,
                             float* __restrict__ out) {
    const int cid = blockIdx.x;
    const int b = cid / SS, s = cid % SS;
    __shared__ int   sidx[KK];
    __shared__ float rel[3][KK];
    __shared__ float sf[KK][CC + 1];
    const int tid = threadIdx.x;

    if (tid < KK) {
        const int id = g_ballidx[(size_t)cid * KK + tid];
        sidx[tid] = id;
        const float* c = out + (size_t)cid * 3;
        const float* p = xyz + ((size_t)b * NN + id) * 3;
        rel[0][tid] = p[0] - c[0];
        rel[1][tid] = p[1] - c[1];
        rel[2][tid] = p[2] - c[2];
    }
    __syncthreads();

    const int cch = tid & 63;
    const int k0  = tid >> 6;   // 0..3
    const float* ftb = g_ft + (size_t)b * NN * CC;
#pragma unroll
    for (int j = 0; j < 8; j++) {
        const int k = k0 * 8 + j;
        sf[k][cch] = ftb[(size_t)sidx[k] * CC + cch];
    }
    __syncthreads();

    float* og = out + GROUPED_OFF + (size_t)b * (CC + 3) * SS * KK + (size_t)s * KK;
    if (tid < 96) {
        const int ch = tid >> 5, k = tid & 31;
        og[(size_t)ch * (SS * KK) + k] = rel[ch][k];
    }
    const int k  = tid & 31;
    const int cg = tid >> 5;    // 0..7
#pragma unroll
    for (int j = 0; j < 8; j++) {
        const int c2 = cg * 8 + j;
        og[(size_t)(3 + c2) * (SS * KK) + k] = sf[k][c2];
    }
}

// ---------------------------------------------------------------------------
extern "C" void kernel_launch(void* const* d_in, const int* in_sizes, int n_in,
                              void* d_out, int out_size) {
    const float* xyz  = (const float*)d_in[0];
    const float* feat = (const float*)d_in[1];
    float* out = (float*)d_out;

    transpose_kernel<<<dim3(NN / 32, CC / 32, BB), dim3(32, 8)>>>(feat);
    fps_kernel<<<BB * CLU, 256>>>(xyz, out);
    ballquery_kernel<<<(BB * SS) / 8, 256>>>(xyz, out);
    group_kernel<<<BB * SS, 256>>>(xyz, out);
}

// round 5
// speedup vs baseline: 1.6737x; 1.6737x over previous
#include <cuda_runtime.h>
#include <cstddef>
#include <cstdint>

#define BB 4
#define NN 8192
#define CC 64
#define SS 2048
#define KK 32
#define R2 0.04f

#define GROUPED_OFF (BB * SS * 3)                       /* 24576 */
#define FPS_OFF (GROUPED_OFF + BB * (CC + 3) * SS * KK) /* 24576 + 17563648 */

// scratch (static device globals: no allocation in kernel_launch)
__device__ int   g_ballidx[BB * SS * KK];    // 1 MB
__device__ float g_ft[(size_t)BB * NN * CC]; // 8 MB, features transposed to (B,N,C)

// ---------------------------------------------------------------------------
// packed f32x2 helpers (Blackwell FFMA2 path — only reachable via PTX f32x2)
// ---------------------------------------------------------------------------
typedef unsigned long long u64;

__device__ __forceinline__ u64 pk2(float lo, float hi) {
    u64 r; asm("mov.b64 %0, {%1, %2};" : "=l"(r) : "f"(lo), "f"(hi)); return r;
}
__device__ __forceinline__ void upk2(u64 v, float& lo, float& hi) {
    asm("mov.b64 {%0, %1}, %2;" : "=f"(lo), "=f"(hi) : "l"(v));
}
__device__ __forceinline__ u64 add2(u64 a, u64 b) {
    u64 r; asm("add.rn.f32x2 %0, %1, %2;" : "=l"(r) : "l"(a), "l"(b)); return r;
}
__device__ __forceinline__ u64 mul2(u64 a, u64 b) {
    u64 r; asm("mul.rn.f32x2 %0, %1, %2;" : "=l"(r) : "l"(a), "l"(b)); return r;
}
__device__ __forceinline__ u64 fma2(u64 a, u64 b, u64 c) {
    u64 r; asm("fma.rn.f32x2 %0, %1, %2, %3;" : "=l"(r) : "l"(a), "l"(b), "l"(c)); return r;
}

// ---------------------------------------------------------------------------
// features (B,C,N) -> (B,N,C)
// ---------------------------------------------------------------------------
__global__ void transpose_kernel(const float* __restrict__ f) {
    __shared__ float tile[32][33];
    const int b  = blockIdx.z;
    const int n0 = blockIdx.x * 32;
    const int c0 = blockIdx.y * 32;
    const float* fb = f + (size_t)b * CC * NN;
#pragma unroll
    for (int j = 0; j < 32; j += 8)
        tile[threadIdx.y + j][threadIdx.x] =
            fb[(size_t)(c0 + threadIdx.y + j) * NN + (n0 + threadIdx.x)];
    __syncthreads();
    float* fo = g_ft + (size_t)b * NN * CC;
#pragma unroll
    for (int j = 0; j < 32; j += 8)
        fo[(size_t)(n0 + threadIdx.y + j) * CC + (c0 + threadIdx.x)] =
            tile[threadIdx.x][threadIdx.y + j];
}

// ---------------------------------------------------------------------------
// FPS: one block of 256 threads per batch, 32 points per thread.
// Two-phase argmax: value-only fast path (REDUX + leader slots), lazy index
// resolution by the matching thread(s) via 4-chain scan + smem atomicMin.
// Double-buffered slots; two barriers per iteration.
// writes new_xyz (out[0..]) and fps_idx (out[FPS_OFF..], as float)
// ---------------------------------------------------------------------------
__global__ void __launch_bounds__(256, 1)
fps_kernel(const float* __restrict__ xyz, float* __restrict__ out) {
    const int b = blockIdx.x;
    const float* base = xyz + (size_t)b * NN * 3;
    float* newxyz = out + (size_t)b * SS * 3;
    float* fpsout = out + FPS_OFF + (size_t)b * SS;
    const int t = threadIdx.x;
    const int lane = t & 31;

    // pair j holds points (t + 2j*256, t + (2j+1)*256), stored NEGATED
    u64 npx[16], npy[16], npz[16];
    float md[32];
#pragma unroll
    for (int j = 0; j < 16; j++) {
        const int p0 = t + (2 * j) * 256;
        const int p1 = t + (2 * j + 1) * 256;
        npx[j] = pk2(-base[p0 * 3 + 0], -base[p1 * 3 + 0]);
        npy[j] = pk2(-base[p0 * 3 + 1], -base[p1 * 3 + 1]);
        npz[j] = pk2(-base[p0 * 3 + 2], -base[p1 * 3 + 2]);
        md[2 * j] = 1e10f; md[2 * j + 1] = 1e10f;
    }

    __shared__ unsigned s_val[2][32];   // [buf][warp], slots 8..31 stay 0
    __shared__ int      s_gi[2];        // [buf] winning global index
    if (t < 32) { s_val[0][t] = 0u; s_val[1][t] = 0u; }
    // ordered before first read by bar1 of iteration 1

    float cx = base[0], cy = base[1], cz = base[2];
    if (t == 0) {
        fpsout[0] = 0.0f;
        newxyz[0] = cx; newxyz[1] = cy; newxyz[2] = cz;
    }

    for (int i = 1; i < SS; i++) {
        const int buf = i & 1;
        if (t == 0) s_gi[buf] = 0x7fffffff;   // reset BEFORE bar1
        const u64 cx2 = pk2(cx, cx);
        const u64 cy2 = pk2(cy, cy);
        const u64 cz2 = pk2(cz, cz);

        float m2[16];
#pragma unroll
        for (int j = 0; j < 16; j++) {
            const u64 dx = add2(cx2, npx[j]);          // cx - px
            const u64 dy = add2(cy2, npy[j]);
            const u64 dz = add2(cz2, npz[j]);
            const u64 d  = fma2(dz, dz, fma2(dy, dy, mul2(dx, dx)));
            float dl, dh; upk2(d, dl, dh);
            md[2 * j]     = fminf(md[2 * j], dl);
            md[2 * j + 1] = fminf(md[2 * j + 1], dh);
            m2[j] = fmaxf(md[2 * j], md[2 * j + 1]);
        }
        float m4[8];
#pragma unroll
        for (int j = 0; j < 8; j++) m4[j] = fmaxf(m2[2 * j], m2[2 * j + 1]);
        float m8[4];
#pragma unroll
        for (int j = 0; j < 4; j++) m8[j] = fmaxf(m4[2 * j], m4[2 * j + 1]);
        const float bv = fmaxf(fmaxf(m8[0], m8[1]), fmaxf(m8[2], m8[3]));

        // value-only warp reduce (md >= 0: float bits order-isomorphic to u32)
        const unsigned ubv  = __float_as_uint(bv);
        const unsigned wmax = __reduce_max_sync(0xffffffffu, ubv);
        if (lane == 0) s_val[buf][t >> 5] = wmax;
        __syncthreads();                                   // bar1

        // block max from the 8 leader slots (pads = 0 always lose)
        const unsigned bmax = __reduce_max_sync(0xffffffffu, s_val[buf][lane]);

        // lazy index resolution: only max-holding thread(s) scan
        if (ubv == bmax) {
            int c0 = 0x7fffffff, c1 = 0x7fffffff, c2 = 0x7fffffff, c3 = 0x7fffffff;
#pragma unroll
            for (int k = 7; k >= 0; k--) {                 // descending keeps lowest k
                if (md[k]      == bv) c0 = t + k * 256;
                if (md[k + 8]  == bv) c1 = t + (k + 8) * 256;
                if (md[k + 16] == bv) c2 = t + (k + 16) * 256;
                if (md[k + 24] == bv) c3 = t + (k + 24) * 256;
            }
            const int bi = min(min(c0, c1), min(c2, c3));  // lowest global idx
            atomicMin(&s_gi[buf], bi);                     // ties across threads
        }
        __syncthreads();                                   // bar2

        const int gi = s_gi[buf];
        cx = base[(size_t)gi * 3 + 0];   // same addr per warp -> L1 broadcast
        cy = base[(size_t)gi * 3 + 1];
        cz = base[(size_t)gi * 3 + 2];
        if (t == 0) {
            fpsout[i] = (float)gi;
            newxyz[(size_t)i * 3 + 0] = cx;
            newxyz[(size_t)i * 3 + 1] = cy;
            newxyz[(size_t)i * 3 + 2] = cz;
        }
    }
}

// ---------------------------------------------------------------------------
// ball query: one warp per center; first K hits in index order via ballot/popc,
// pad with first hit (0 if none). Early exit when K found.
// ---------------------------------------------------------------------------
__global__ void ballquery_kernel(const float* __restrict__ xyz,
                                 const float* __restrict__ out) {
    __shared__ int sidx[8][KK];
    const int w    = threadIdx.x >> 5;
    const int lane = threadIdx.x & 31;
    const int cid  = blockIdx.x * 8 + w;
    const int b = cid / SS;
    const float* c = out + (size_t)cid * 3;      // new_xyz lives at start of out
    const float cx = c[0], cy = c[1], cz = c[2];
    const float* base = xyz + (size_t)b * NN * 3;

    sidx[w][lane] = 0;
    int cnt = 0;
    for (int p0 = 0; p0 < NN && cnt < KK; p0 += 32) {
        const int p = p0 + lane;
        const float dx = base[p * 3 + 0] - cx;
        const float dy = base[p * 3 + 1] - cy;
        const float dz = base[p * 3 + 2] - cz;
        const float d2 = __fmaf_rn(dz, dz, __fmaf_rn(dy, dy, __fmul_rn(dx, dx)));
        const bool hit = d2 < R2;
        const unsigned m = __ballot_sync(0xffffffffu, hit);
        if (m) {
            if (cnt == 0) {
                const int first = p0 + (__ffs(m) - 1);
                sidx[w][lane] = first;      // pad all K slots with first hit
            }
            __syncwarp();
            if (hit) {
                const int slot = cnt + __popc(m & ((1u << lane) - 1u));
                if (slot < KK) sidx[w][slot] = p;
            }
            cnt += __popc(m);
        }
    }
    __syncwarp();
    g_ballidx[(size_t)cid * KK + lane] = sidx[w][lane];
}

// ---------------------------------------------------------------------------
// grouping: one block per center. Coalesced 256B feature-row reads via smem,
// coalesced K-contiguous channel-major writes.
// out grouped layout: (B, 3+C, S, K), channels 0..2 = recentered xyz
// ---------------------------------------------------------------------------
__global__ void group_kernel(const float* __restrict__ xyz,
                             float* __restrict__ out) {
    const int cid = blockIdx.x;
    const int b = cid / SS, s = cid % SS;
    __shared__ int   sidx[KK];
    __shared__ float rel[3][KK];
    __shared__ float sf[KK][CC + 1];
    const int tid = threadIdx.x;

    if (tid < KK) {
        const int id = g_ballidx[(size_t)cid * KK + tid];
        sidx[tid] = id;
        const float* c = out + (size_t)cid * 3;
        const float* p = xyz + ((size_t)b * NN + id) * 3;
        rel[0][tid] = p[0] - c[0];
        rel[1][tid] = p[1] - c[1];
        rel[2][tid] = p[2] - c[2];
    }
    __syncthreads();

    const int cch = tid & 63;
    const int k0  = tid >> 6;   // 0..3
    const float* ftb = g_ft + (size_t)b * NN * CC;
#pragma unroll
    for (int j = 0; j < 8; j++) {
        const int k = k0 * 8 + j;
        sf[k][cch] = ftb[(size_t)sidx[k] * CC + cch];
    }
    __syncthreads();

    float* og = out + GROUPED_OFF + (size_t)b * (CC + 3) * SS * KK + (size_t)s * KK;
    if (tid < 96) {
        const int ch = tid >> 5, k = tid & 31;
        og[(size_t)ch * (SS * KK) + k] = rel[ch][k];
    }
    const int k  = tid & 31;
    const int cg = tid >> 5;    // 0..7
#pragma unroll
    for (int j = 0; j < 8; j++) {
        const int c2 = cg * 8 + j;
        og[(size_t)(3 + c2) * (SS * KK) + k] = sf[k][c2];
    }
}

// ---------------------------------------------------------------------------
extern "C" void kernel_launch(void* const* d_in, const int* in_sizes, int n_in,
                              void* d_out, int out_size) {
    const float* xyz  = (const float*)d_in[0];
    const float* feat = (const float*)d_in[1];
    float* out = (float*)d_out;

    transpose_kernel<<<dim3(NN / 32, CC / 32, BB), dim3(32, 8)>>>(feat);
    fps_kernel<<<BB, 256>>>(xyz, out);
    ballquery_kernel<<<(BB * SS) / 8, 256>>>(xyz, out);
    group_kernel<<<BB * SS, 256>>>(xyz, out);
}